// round 1
// baseline (speedup 1.0000x reference)
#include <cuda_runtime.h>
#include <math.h>

// ---------------------------------------------------------------------------
// Problem constants
// ---------------------------------------------------------------------------
#define BATCH   2
#define SEQ     2048
#define DMODEL  1024
#define HEADS   16
#define DHEAD   64
#define INNER   (HEADS * DHEAD)      // 1024
#define ROWS    (BATCH * SEQ)        // 4096
#define ATTN_EPS 1e-8f

// Scratch (device globals: allowed; runtime alloc is not)
__device__ float g_q  [ROWS * INNER];        // 16 MB
__device__ float g_kv [ROWS * 2 * INNER];    // 32 MB
__device__ float g_att[ROWS * INNER];        // 16 MB

// ---------------------------------------------------------------------------
// SGEMM: C[M,N] = A[M,K] @ B[K,N] (+ bias[N] if bias != nullptr)
// 128x128 block, BK=8, 8x8 microtile, 256 threads.
// ---------------------------------------------------------------------------
__global__ __launch_bounds__(256)
void sgemm_kernel(const float* __restrict__ A, const float* __restrict__ B,
                  const float* __restrict__ bias, float* __restrict__ C,
                  int M, int N, int K)
{
    __shared__ float As[8][132];   // transposed A tile, padded
    __shared__ float Bs[8][128];

    const int tid = threadIdx.x;
    const int tx = tid & 15;            // 0..15 -> 8 cols each
    const int ty = tid >> 4;            // 0..15 -> 8 rows each
    const int blockRow = blockIdx.y * 128;
    const int blockCol = blockIdx.x * 128;

    const int arow = tid >> 1;          // 0..127
    const int acol = (tid & 1) * 4;     // 0 or 4
    const int brow = tid >> 5;          // 0..7
    const int bcol = (tid & 31) * 4;    // 0..124

    float acc[8][8];
    #pragma unroll
    for (int i = 0; i < 8; i++)
        #pragma unroll
        for (int j = 0; j < 8; j++) acc[i][j] = 0.f;

    for (int k0 = 0; k0 < K; k0 += 8) {
        float4 av = *(const float4*)(A + (size_t)(blockRow + arow) * K + k0 + acol);
        float4 bv = *(const float4*)(B + (size_t)(k0 + brow) * N + blockCol + bcol);
        As[acol + 0][arow] = av.x;
        As[acol + 1][arow] = av.y;
        As[acol + 2][arow] = av.z;
        As[acol + 3][arow] = av.w;
        *(float4*)&Bs[brow][bcol] = bv;
        __syncthreads();

        #pragma unroll
        for (int kk = 0; kk < 8; kk++) {
            float rm[8], rn[8];
            *(float4*)&rm[0] = *(const float4*)&As[kk][ty * 8];
            *(float4*)&rm[4] = *(const float4*)&As[kk][ty * 8 + 4];
            *(float4*)&rn[0] = *(const float4*)&Bs[kk][tx * 8];
            *(float4*)&rn[4] = *(const float4*)&Bs[kk][tx * 8 + 4];
            #pragma unroll
            for (int i = 0; i < 8; i++)
                #pragma unroll
                for (int j = 0; j < 8; j++)
                    acc[i][j] += rm[i] * rn[j];
        }
        __syncthreads();
    }

    #pragma unroll
    for (int i = 0; i < 8; i++) {
        const int row = blockRow + ty * 8 + i;
        #pragma unroll
        for (int j4 = 0; j4 < 8; j4 += 4) {
            const int col = blockCol + tx * 8 + j4;
            float4 r;
            r.x = acc[i][j4 + 0];
            r.y = acc[i][j4 + 1];
            r.z = acc[i][j4 + 2];
            r.w = acc[i][j4 + 3];
            if (bias) {
                r.x += bias[col + 0];
                r.y += bias[col + 1];
                r.z += bias[col + 2];
                r.w += bias[col + 3];
            }
            *(float4*)(C + (size_t)row * N + col) = r;
        }
    }
}

// ---------------------------------------------------------------------------
// Flash-style causal attention with UNMASKED row max (matches reference gm):
//   m = running max over raw scores for ALL j; p = exp(s - m) with causal mask;
//   out = (sum p*v) / (sum p + eps)
// Grid: (SEQ/128, BATCH*HEADS). 128 threads: 16x8 thread grid, 8x8 microtiles.
// Br = 128 query rows, Bc = 64 key rows per tile.
// ---------------------------------------------------------------------------
#define ATTN_SMEM_FLOATS (64*128 + 64*64 + 64*64 + 128*65)
#define ATTN_SMEM_BYTES  (ATTN_SMEM_FLOATS * 4)

__global__ __launch_bounds__(128, 2)
void attn_kernel(const float* __restrict__ gq, const float* __restrict__ gkv,
                 float* __restrict__ gout)
{
    extern __shared__ float sm[];
    float* Qst = sm;                 // [64][128]  d-major, swizzled cols
    float* Kst = Qst + 64 * 128;     // [64][64]   d-major, swizzled cols
    float* Vs  = Kst + 64 * 64;      // [64][64]   row-major (j, d)
    float* Ps  = Vs  + 64 * 64;      // [128][65]  P, 3-bit-swapped col layout

    const int tid = threadIdx.x;
    const int tr = tid >> 3;         // 0..15 : owns rows tr*8 .. tr*8+7
    const int tc = tid & 7;          // 0..7  : owns cols tc*8 .. tc*8+7
    const int b  = blockIdx.y >> 4;
    const int h  = blockIdx.y & 15;
    const int qstart = blockIdx.x * 128;

    const float* qbase = gq  + ((size_t)b * SEQ + qstart) * INNER + h * DHEAD;
    const float* kvb   = gkv + (size_t)b * SEQ * (2 * INNER) + h * DHEAD;

    // ---- load Q tile (scaled by Dh^-0.5 = 0.125), transposed + swizzled ----
    #pragma unroll
    for (int it = 0; it < 16; it++) {
        int id  = tid + it * 128;        // 0..2047
        int d4  = id & 15;
        int row = id >> 4;               // 0..127
        float4 v = *(const float4*)(qbase + (size_t)row * INNER + d4 * 4);
        int sw = (d4 & 7) << 3;
        int pr = row ^ sw;
        Qst[(4 * d4 + 0) * 128 + pr] = v.x * 0.125f;
        Qst[(4 * d4 + 1) * 128 + pr] = v.y * 0.125f;
        Qst[(4 * d4 + 2) * 128 + pr] = v.z * 0.125f;
        Qst[(4 * d4 + 3) * 128 + pr] = v.w * 0.125f;
    }

    float o[8][8];
    float m[8], l[8];
    #pragma unroll
    for (int i = 0; i < 8; i++) {
        m[i] = -INFINITY; l[i] = 0.f;
        #pragma unroll
        for (int j = 0; j < 8; j++) o[i][j] = 0.f;
    }

    for (int jt = 0; jt < 32; jt++) {
        const int jstart = jt * 64;
        __syncthreads();   // previous tile's reads of Kst/Vs/Ps done

        // ---- load K (transposed+swizzled) and V (row-major) tiles ----
        #pragma unroll
        for (int it = 0; it < 8; it++) {
            int id = tid + it * 128;     // 0..1023
            int d4 = id & 15;
            int j  = id >> 4;            // 0..63
            const float* src = kvb + (size_t)(jstart + j) * (2 * INNER) + d4 * 4;
            float4 k4 = *(const float4*)(src);
            float4 v4 = *(const float4*)(src + INNER);
            int sw = (d4 & 7) << 3;
            int pj = j ^ sw;
            Kst[(4 * d4 + 0) * 64 + pj] = k4.x;
            Kst[(4 * d4 + 1) * 64 + pj] = k4.y;
            Kst[(4 * d4 + 2) * 64 + pj] = k4.z;
            Kst[(4 * d4 + 3) * 64 + pj] = k4.w;
            *(float4*)(Vs + j * 64 + d4 * 4) = v4;
        }
        __syncthreads();

        // ---- S = Q @ K^T, 8x8 frag per thread ----
        float s[8][8];
        #pragma unroll
        for (int i = 0; i < 8; i++)
            #pragma unroll
            for (int j = 0; j < 8; j++) s[i][j] = 0.f;

        #pragma unroll 4
        for (int d = 0; d < 64; d++) {
            int sw = ((d >> 2) & 7) << 3;
            int qb = (tr * 8) ^ sw;
            int kb = (tc * 8) ^ sw;
            float qv[8], kv[8];
            *(float4*)&qv[0] = *(const float4*)&Qst[d * 128 + qb];
            *(float4*)&qv[4] = *(const float4*)&Qst[d * 128 + qb + 4];
            *(float4*)&kv[0] = *(const float4*)&Kst[d * 64 + kb];
            *(float4*)&kv[4] = *(const float4*)&Kst[d * 64 + kb + 4];
            #pragma unroll
            for (int i = 0; i < 8; i++)
                #pragma unroll
                for (int j = 0; j < 8; j++)
                    s[i][j] += qv[i] * kv[j];
        }

        // ---- online softmax stats (max over raw UNMASKED scores) ----
        float al[8];
        #pragma unroll
        for (int i = 0; i < 8; i++) {
            float mx = s[i][0];
            #pragma unroll
            for (int j = 1; j < 8; j++) mx = fmaxf(mx, s[i][j]);
            #pragma unroll
            for (int off = 1; off < 8; off <<= 1)
                mx = fmaxf(mx, __shfl_xor_sync(0xffffffffu, mx, off));
            float mn = fmaxf(m[i], mx);
            al[i] = __expf(m[i] - mn);
            m[i]  = mn;
        }

        const bool active = (jstart <= qstart + 127);  // uniform over block

        if (active) {
            const int ig0 = qstart + tr * 8;
            const int jg0 = jstart + tc * 8;
            #pragma unroll
            for (int i = 0; i < 8; i++) {
                float r = 0.f;
                #pragma unroll
                for (int j = 0; j < 8; j++) {
                    float p = (jg0 + j <= ig0 + i) ? __expf(s[i][j] - m[i]) : 0.f;
                    s[i][j] = p;
                    r += p;
                }
                #pragma unroll
                for (int off = 1; off < 8; off <<= 1)
                    r += __shfl_xor_sync(0xffffffffu, r, off);
                l[i] = l[i] * al[i] + r;
            }
        } else {
            #pragma unroll
            for (int i = 0; i < 8; i++) l[i] *= al[i];
        }

        #pragma unroll
        for (int i = 0; i < 8; i++)
            #pragma unroll
            for (int j = 0; j < 8; j++)
                o[i][j] *= al[i];

        if (active) {
            // store P frag; physical col = ((c&7)<<3)|(c>>3), c = tc*8+j
            #pragma unroll
            for (int i = 0; i < 8; i++)
                #pragma unroll
                for (int j = 0; j < 8; j++)
                    Ps[(tr * 8 + i) * 65 + (j * 8 + tc)] = s[i][j];
            __syncthreads();

            // ---- O += P @ V ----
            #pragma unroll 2
            for (int jj = 0; jj < 64; jj++) {
                int pj = ((jj & 7) << 3) | (jj >> 3);
                float pv[8];
                #pragma unroll
                for (int i = 0; i < 8; i++)
                    pv[i] = Ps[(tr * 8 + i) * 65 + pj];
                float vv[8];
                *(float4*)&vv[0] = *(const float4*)&Vs[jj * 64 + tc * 8];
                *(float4*)&vv[4] = *(const float4*)&Vs[jj * 64 + tc * 8 + 4];
                #pragma unroll
                for (int i = 0; i < 8; i++)
                    #pragma unroll
                    for (int j = 0; j < 8; j++)
                        o[i][j] += pv[i] * vv[j];
            }
        }
    }

    // ---- epilogue: divide by (l + eps), write (b, n, h*Dh + d) ----
    float* ob = gout + ((size_t)b * SEQ + qstart + tr * 8) * INNER + h * DHEAD + tc * 8;
    #pragma unroll
    for (int i = 0; i < 8; i++) {
        float inv = 1.0f / (l[i] + ATTN_EPS);
        float4 r0, r1;
        r0.x = o[i][0] * inv; r0.y = o[i][1] * inv;
        r0.z = o[i][2] * inv; r0.w = o[i][3] * inv;
        r1.x = o[i][4] * inv; r1.y = o[i][5] * inv;
        r1.z = o[i][6] * inv; r1.w = o[i][7] * inv;
        *(float4*)(ob + (size_t)i * INNER)     = r0;
        *(float4*)(ob + (size_t)i * INNER + 4) = r1;
    }
}

// ---------------------------------------------------------------------------
// Launch
// ---------------------------------------------------------------------------
extern "C" void kernel_launch(void* const* d_in, const int* in_sizes, int n_in,
                              void* d_out, int out_size)
{
    const float* x   = (const float*)d_in[0];
    const float* Wq  = (const float*)d_in[1];
    const float* Wkv = (const float*)d_in[2];
    const float* Wo  = (const float*)d_in[3];
    const float* bo  = (const float*)d_in[4];
    float* out = (float*)d_out;

    float *pq, *pkv, *patt;
    cudaGetSymbolAddress((void**)&pq,   g_q);
    cudaGetSymbolAddress((void**)&pkv,  g_kv);
    cudaGetSymbolAddress((void**)&patt, g_att);

    cudaFuncSetAttribute(attn_kernel,
                         cudaFuncAttributeMaxDynamicSharedMemorySize,
                         ATTN_SMEM_BYTES);

    // q = x @ Wq   (4096x1024 @ 1024x1024)
    sgemm_kernel<<<dim3(INNER / 128, ROWS / 128), 256>>>(
        x, Wq, nullptr, pq, ROWS, INNER, DMODEL);

    // kv = x @ Wkv (4096x1024 @ 1024x2048)
    sgemm_kernel<<<dim3(2 * INNER / 128, ROWS / 128), 256>>>(
        x, Wkv, nullptr, pkv, ROWS, 2 * INNER, DMODEL);

    // attention -> g_att (b, n, h*dh)
    attn_kernel<<<dim3(SEQ / 128, BATCH * HEADS), 128, ATTN_SMEM_BYTES>>>(
        pq, pkv, patt);

    // out = att @ Wo + bo
    sgemm_kernel<<<dim3(DMODEL / 128, ROWS / 128), 256>>>(
        patt, Wo, bo, out, ROWS, DMODEL, INNER);
}